// round 13
// baseline (speedup 1.0000x reference)
#include <cuda_runtime.h>
#include <cuda_fp16.h>
#include <math.h>
#include <stdint.h>

#define DIM 1536
#define NH 12
#define HD 128
#define MAXS 2048
#define MAX_ATTN_W 32760
#define LWMAX 8192       // max materialized window (tokens)
#define GSTR 40          // GEMM smem row stride (halfs)
#define ASTR 136         // attention smem row stride (halfs)
#define ABUF (64 * ASTR) // one K or V tile buffer (halfs)
#define SOFTMAX_SHIFT 6.0f

__device__ float  g_q[MAXS * DIM];
__device__ float  g_k[MAXS * DIM];
__device__ float  g_v[MAXS * DIM];
__device__ __half g_x16[MAXS * DIM];
__device__ __half g_q16[MAXS * DIM];
__device__ __half g_o16[MAXS * DIM];
__device__ __half g_wq16[DIM * DIM];
__device__ __half g_wk16[DIM * DIM];
__device__ __half g_wv16[DIM * DIM];
__device__ __half g_wo16[DIM * DIM];
__device__ __half g_ku[(size_t)NH * LWMAX * HD];
__device__ __half g_vu[(size_t)NH * LWMAX * HD];

// ---------------------------------------------------------------------------
__device__ __forceinline__ uint32_t smem_u32(const void* p) {
    uint32_t a;
    asm("{ .reg .u64 t; cvta.to.shared.u64 t, %1; cvt.u32.u64 %0, t; }" : "=r"(a) : "l"(p));
    return a;
}
__device__ __forceinline__ uint32_t pkh(float a, float b) {
    __half2 h = __floats2half2_rn(a, b);
    return *(uint32_t*)&h;
}
__device__ __forceinline__ void mma16(float* d, const uint32_t* a, uint32_t b0, uint32_t b1) {
    asm volatile(
        "mma.sync.aligned.m16n8k16.row.col.f32.f16.f16.f32 "
        "{%0,%1,%2,%3},{%4,%5,%6,%7},{%8,%9},{%0,%1,%2,%3};"
        : "+f"(d[0]), "+f"(d[1]), "+f"(d[2]), "+f"(d[3])
        : "r"(a[0]), "r"(a[1]), "r"(a[2]), "r"(a[3]), "r"(b0), "r"(b1));
}
__device__ __forceinline__ void ldsm4(uint32_t& r0, uint32_t& r1, uint32_t& r2, uint32_t& r3,
                                      uint32_t a) {
    asm volatile("ldmatrix.sync.aligned.m8n8.x4.shared.b16 {%0,%1,%2,%3}, [%4];"
                 : "=r"(r0), "=r"(r1), "=r"(r2), "=r"(r3) : "r"(a));
}
__device__ __forceinline__ void ldsm4t(uint32_t& r0, uint32_t& r1, uint32_t& r2, uint32_t& r3,
                                       uint32_t a) {
    asm volatile("ldmatrix.sync.aligned.m8n8.x4.trans.shared.b16 {%0,%1,%2,%3}, [%4];"
                 : "=r"(r0), "=r"(r1), "=r"(r2), "=r"(r3) : "r"(a));
}
__device__ __forceinline__ void cp16(uint32_t dst, const void* src) {
    asm volatile("cp.async.cg.shared.global [%0], [%1], 16;" :: "r"(dst), "l"(src));
}
__device__ __forceinline__ void cp16z(uint32_t dst, const void* src, int sz) {
    asm volatile("cp.async.cg.shared.global [%0], [%1], 16, %2;" :: "r"(dst), "l"(src), "r"(sz));
}
#define CP_COMMIT() asm volatile("cp.async.commit_group;" ::: "memory")
#define CP_WAIT(n)  asm volatile("cp.async.wait_group %0;" :: "n"(n) : "memory")

// ---------------------------------------------------------------------------
// fused fp32 -> fp16 conversion for x + 4 weight matrices (grid.y selects)
// ---------------------------------------------------------------------------
__global__ void cvt16_all(
    const float* __restrict__ x,  __half* __restrict__ x16,  int xn4,
    const float* __restrict__ w0, __half* __restrict__ o0,
    const float* __restrict__ w1, __half* __restrict__ o1,
    const float* __restrict__ w2, __half* __restrict__ o2,
    const float* __restrict__ w3, __half* __restrict__ o3, int wn4)
{
    const float* in; __half* out; int n4;
    switch (blockIdx.y) {
        case 0: in = x;  out = x16; n4 = xn4; break;
        case 1: in = w0; out = o0;  n4 = wn4; break;
        case 2: in = w1; out = o1;  n4 = wn4; break;
        case 3: in = w2; out = o2;  n4 = wn4; break;
        default: in = w3; out = o3; n4 = wn4; break;
    }
    int i = blockIdx.x * blockDim.x + threadIdx.x;
    if (i < n4) {
        float4 v = ((const float4*)in)[i];
        ((__half2*)out)[2 * i]     = __floats2half2_rn(v.x, v.y);
        ((__half2*)out)[2 * i + 1] = __floats2half2_rn(v.z, v.w);
    }
}

// ---------------------------------------------------------------------------
// fp16 GEMM, BM=128 (R6-proven) — used for the O projection (single wave).
// ---------------------------------------------------------------------------
__device__ __forceinline__ void gemm_stage(
    const __half* __restrict__ A, const __half* __restrict__ W,
    uint32_t sa, uint32_t sw, int kc, int m0, int n0, int M, int t)
{
#pragma unroll
    for (int i = 0; i < 2; i++) {
        const int id = t + i * 256;
        const int row = id >> 2, slot = id & 3;
        const int ar = m0 + row;
        const __half* asrc = A + (size_t)(ar < M ? ar : 0) * DIM + kc * 32 + slot * 8;
        cp16z(sa + (uint32_t)(row * GSTR + slot * 8) * 2, asrc, ar < M ? 16 : 0);
        cp16(sw + (uint32_t)(row * GSTR + slot * 8) * 2,
             W + (size_t)(n0 + row) * DIM + kc * 32 + slot * 8);
    }
    CP_COMMIT();
}

__global__ __launch_bounds__(256, 2) void gemm_h16(
    const __half* __restrict__ A,
    const __half* __restrict__ W, const float* __restrict__ Bi, float* __restrict__ Y,
    int M)
{
    __shared__ __half SA[2][128 * GSTR];
    __shared__ __half SW[2][128 * GSTR];

    const int t = threadIdx.x, l = t & 31, wid = t >> 5;
    const int wm = (wid & 3) * 32, wn = (wid >> 2) * 64;
    const int g = l >> 2, tg = l & 3;
    const int m0 = blockIdx.x * 128, n0 = blockIdx.y * 128;

    const uint32_t saw[2] = { smem_u32(SA[0]), smem_u32(SA[1]) };
    const uint32_t sww[2] = { smem_u32(SW[0]), smem_u32(SW[1]) };

    const int a_row = (l & 7) + 8 * ((l >> 3) & 1);
    const int a_half = 8 * ((l >> 4) & 1);
    const int b_row = (l & 7) + 8 * ((l >> 4) & 1);
    const int b_half = 8 * ((l >> 3) & 1);

    float acc[2][8][4];
#pragma unroll
    for (int i = 0; i < 2; i++)
#pragma unroll
        for (int j = 0; j < 8; j++)
#pragma unroll
            for (int c = 0; c < 4; c++) acc[i][j][c] = 0.0f;

    gemm_stage(A, W, saw[0], sww[0], 0, m0, n0, M, t);

    for (int kc = 0; kc < DIM / 32; kc++) {
        const int b = kc & 1;
        if (kc + 1 < DIM / 32) {
            gemm_stage(A, W, saw[1 - b], sww[1 - b], kc + 1, m0, n0, M, t);
            CP_WAIT(1);
        } else {
            CP_WAIT(0);
        }
        __syncthreads();

        const uint32_t ab = saw[b], wb = sww[b];
#pragma unroll
        for (int ks = 0; ks < 2; ks++) {
            uint32_t af[2][4];
            ldsm4(af[0][0], af[0][1], af[0][2], af[0][3],
                  ab + (uint32_t)((wm + a_row) * GSTR + 16 * ks + a_half) * 2);
            ldsm4(af[1][0], af[1][1], af[1][2], af[1][3],
                  ab + (uint32_t)((wm + 16 + a_row) * GSTR + 16 * ks + a_half) * 2);
#pragma unroll
            for (int j = 0; j < 4; j++) {
                uint32_t b0, b1, b2, b3;
                ldsm4(b0, b1, b2, b3,
                      wb + (uint32_t)((wn + 16 * j + b_row) * GSTR + 16 * ks + b_half) * 2);
                mma16(acc[0][2 * j],     af[0], b0, b1);
                mma16(acc[0][2 * j + 1], af[0], b2, b3);
                mma16(acc[1][2 * j],     af[1], b0, b1);
                mma16(acc[1][2 * j + 1], af[1], b2, b3);
            }
        }
        __syncthreads();
    }

#pragma unroll
    for (int mt = 0; mt < 2; mt++) {
        const int r0 = m0 + wm + mt * 16 + g;
#pragma unroll
        for (int nt = 0; nt < 8; nt++) {
            const int cc = n0 + wn + nt * 8 + 2 * tg;
            const float b0 = Bi[cc], b1 = Bi[cc + 1];
            if (r0 < M) {
                float2 v = make_float2(acc[mt][nt][0] + b0, acc[mt][nt][1] + b1);
                *(float2*)&Y[(size_t)r0 * DIM + cc] = v;
            }
            if (r0 + 8 < M) {
                float2 v = make_float2(acc[mt][nt][2] + b0, acc[mt][nt][3] + b1);
                *(float2*)&Y[(size_t)(r0 + 8) * DIM + cc] = v;
            }
        }
    }
}

// ---------------------------------------------------------------------------
// fp16 GEMM, BM=192 x BN=128 — QKV launch (324 CTAs ~ 1.09 waves).
// 8 warps as 4(m) x 2(n): warp tile 48x64.  Dynamic smem 51200 B.
// stage s: A @ s*12800 halfs (192*40), W @ +7680 halfs.
// ---------------------------------------------------------------------------
__device__ __forceinline__ void gemm192_stage(
    const __half* __restrict__ A, const __half* __restrict__ W,
    uint32_t sa, uint32_t sw, int kc, int m0, int n0, int M, int t)
{
#pragma unroll
    for (int i = 0; i < 3; i++) {   // 768 A-chunks
        const int id = t + i * 256;
        const int row = id >> 2, slot = id & 3;
        const int ar = m0 + row;
        const __half* asrc = A + (size_t)(ar < M ? ar : 0) * DIM + kc * 32 + slot * 8;
        cp16z(sa + (uint32_t)(row * GSTR + slot * 8) * 2, asrc, ar < M ? 16 : 0);
    }
#pragma unroll
    for (int i = 0; i < 2; i++) {   // 512 W-chunks
        const int id = t + i * 256;
        const int row = id >> 2, slot = id & 3;
        cp16(sw + (uint32_t)(row * GSTR + slot * 8) * 2,
             W + (size_t)(n0 + row) * DIM + kc * 32 + slot * 8);
    }
    CP_COMMIT();
}

__global__ __launch_bounds__(256, 2) void gemm192_h16(
    const __half* __restrict__ A,
    const __half* __restrict__ W0, const float* __restrict__ B0, float* __restrict__ Y0,
    const __half* __restrict__ W1, const float* __restrict__ B1, float* __restrict__ Y1,
    const __half* __restrict__ W2, const float* __restrict__ B2, float* __restrict__ Y2,
    int M)
{
    extern __shared__ __half gsm[];

    const __half* W; const float* Bi; float* Y;
    if (blockIdx.z == 0)      { W = W0; Bi = B0; Y = Y0; }
    else if (blockIdx.z == 1) { W = W1; Bi = B1; Y = Y1; }
    else                      { W = W2; Bi = B2; Y = Y2; }

    const int t = threadIdx.x, l = t & 31, wid = t >> 5;
    const int wm = (wid & 3) * 48, wn = (wid >> 2) * 64;
    const int g = l >> 2, tg = l & 3;
    const int m0 = blockIdx.x * 192, n0 = blockIdx.y * 128;

    const uint32_t sb = smem_u32(gsm);
    const uint32_t sa[2] = { sb, sb + 12800u * 2u };
    const uint32_t sw[2] = { sb + 7680u * 2u, sb + 20480u * 2u };

    const int a_row = (l & 7) + 8 * ((l >> 3) & 1);
    const int a_half = 8 * ((l >> 4) & 1);
    const int b_row = (l & 7) + 8 * ((l >> 4) & 1);
    const int b_half = 8 * ((l >> 3) & 1);

    float acc[3][8][4];
#pragma unroll
    for (int i = 0; i < 3; i++)
#pragma unroll
        for (int j = 0; j < 8; j++)
#pragma unroll
            for (int c = 0; c < 4; c++) acc[i][j][c] = 0.0f;

    gemm192_stage(A, W, sa[0], sw[0], 0, m0, n0, M, t);

    for (int kc = 0; kc < DIM / 32; kc++) {
        const int b = kc & 1;
        if (kc + 1 < DIM / 32) {
            gemm192_stage(A, W, sa[1 - b], sw[1 - b], kc + 1, m0, n0, M, t);
            CP_WAIT(1);
        } else {
            CP_WAIT(0);
        }
        __syncthreads();

        const uint32_t ab = sa[b], wb = sw[b];
#pragma unroll
        for (int ks = 0; ks < 2; ks++) {
            uint32_t af[3][4];
#pragma unroll
            for (int mt = 0; mt < 3; mt++)
                ldsm4(af[mt][0], af[mt][1], af[mt][2], af[mt][3],
                      ab + (uint32_t)((wm + mt * 16 + a_row) * GSTR + 16 * ks + a_half) * 2);
#pragma unroll
            for (int j = 0; j < 4; j++) {
                uint32_t b0, b1, b2, b3;
                ldsm4(b0, b1, b2, b3,
                      wb + (uint32_t)((wn + 16 * j + b_row) * GSTR + 16 * ks + b_half) * 2);
#pragma unroll
                for (int mt = 0; mt < 3; mt++) {
                    mma16(acc[mt][2 * j],     af[mt], b0, b1);
                    mma16(acc[mt][2 * j + 1], af[mt], b2, b3);
                }
            }
        }
        __syncthreads();
    }

#pragma unroll
    for (int mt = 0; mt < 3; mt++) {
        const int r0 = m0 + wm + mt * 16 + g;
#pragma unroll
        for (int nt = 0; nt < 8; nt++) {
            const int cc = n0 + wn + nt * 8 + 2 * tg;
            const float b0 = Bi[cc], b1 = Bi[cc + 1];
            if (r0 < M) {
                float2 v = make_float2(acc[mt][nt][0] + b0, acc[mt][nt][1] + b1);
                *(float2*)&Y[(size_t)r0 * DIM + cc] = v;
            }
            if (r0 + 8 < M) {
                float2 v = make_float2(acc[mt][nt][2] + b0, acc[mt][nt][3] + b1);
                *(float2*)&Y[(size_t)(r0 + 8) * DIM + cc] = v;
            }
        }
    }
}

// ---------------------------------------------------------------------------
// RMSNorm + RoPE.  q: fp16 into q16 (natural layout).
// k: fp16 into Ku[head][cnw+s][dim].
// ---------------------------------------------------------------------------
__global__ __launch_bounds__(256) void rmsnorm_rope(
    const float* __restrict__ q, const float* __restrict__ k,
    __half* __restrict__ q16, __half* __restrict__ ku,
    const float* __restrict__ gq, const float* __restrict__ gk,
    const float* __restrict__ freqs,
    const int* __restrict__ grid_sizes,
    const int* __restrict__ cur_start_p, int S)
{
    const int s = blockIdx.x;
    const int which = blockIdx.y;
    const float* row = (which ? k : q) + (size_t)s * DIM;
    const float* g = which ? gk : gq;

    __shared__ float red[8];
    __shared__ float cs[64], sn[64];
    const int t = threadIdx.x;

    float ss = 0.0f;
#pragma unroll
    for (int i = 0; i < 6; i++) {
        const float v = row[t + i * 256];
        ss += v * v;
    }
#pragma unroll
    for (int o = 16; o; o >>= 1) ss += __shfl_xor_sync(0xffffffffu, ss, o);
    if ((t & 31) == 0) red[t >> 5] = ss;
    __syncthreads();
    if (t < 8) {
        float v = red[t];
#pragma unroll
        for (int o = 4; o; o >>= 1) v += __shfl_xor_sync(0xffu, v, o);
        if (t == 0) red[0] = v;
    }

    const int Hh = grid_sizes[1];
    const int Ww = grid_sizes[2];
    const int FHW = grid_sizes[0] * Hh * Ww;
    const bool rot = (s < FHW);
    const int cur = cur_start_p[0];
    int ws = cur + S - MAX_ATTN_W; if (ws < 0) ws = 0;
    const int cnw = cur - ws;

    if (rot && t < 64) {
        const int fs = Hh * Ww;
        const int sf = cur / fs;
        const int f = s / fs;
        const int rem = s - f * fs;
        const int h = rem / Ww;
        const int w = rem - h * Ww;
        int idx;
        if (t < 22)       idx = sf + f;
        else if (t < 43)  idx = h;
        else              idx = w;
        const float ang = freqs[idx * 64 + t];
        cs[t] = cosf(ang);
        sn[t] = sinf(ang);
    }
    __syncthreads();

    const float scale = rsqrtf(red[0] * (1.0f / DIM) + 1e-6f);

#pragma unroll
    for (int r = 0; r < 3; r++) {
        const int p = t + r * 256;
        const int j = p & 63;
        const int e0 = 2 * p, e1 = e0 + 1;
        const float a = row[e0] * scale * g[e0];
        const float b = row[e1] * scale * g[e1];
        float o0, o1;
        if (rot) {
            const float c = cs[j], s_ = sn[j];
            o0 = a * c - b * s_;
            o1 = a * s_ + b * c;
        } else {
            o0 = a; o1 = b;
        }
        const uint32_t hv = pkh(o0, o1);
        if (which == 0) {
            *(uint32_t*)&q16[(size_t)s * DIM + e0] = hv;
        } else {
            const int hh = e0 >> 7, d = e0 & 127;
            *(uint32_t*)&ku[((size_t)hh * LWMAX + cnw + s) * HD + d] = hv;
        }
    }
}

// ---------------------------------------------------------------------------
// Materialize fp16 window KV (cache part + pad; V also new part).
// ---------------------------------------------------------------------------
__global__ __launch_bounds__(256) void fill_kv(
    const float* __restrict__ kcache, const float* __restrict__ vcache,
    const float* __restrict__ vnew,
    __half* __restrict__ ku, __half* __restrict__ vu,
    const int* __restrict__ cur_start_p, int S)
{
    const int hh = blockIdx.y;
    const int wt = blockIdx.x;
    const int t = threadIdx.x;

    const int cur = cur_start_p[0];
    int ws = cur + S - MAX_ATTN_W; if (ws < 0) ws = 0;
    const int cnw = cur - ws;
    const int Lw = cur + S - ws;
    const int Lpad = (Lw + 63) & ~63;
    if (wt * 64 >= Lpad) return;

#pragma unroll
    for (int i = 0; i < 8; i++) {
        const int idx = t + i * 256;
        const int tok = idx >> 5;
        const int d4 = (idx & 31) * 4;
        const int w = wt * 64 + tok;

        if (w < cnw) {
            const float4 v = *(const float4*)&kcache[((size_t)(ws + w) * NH + hh) * HD + d4];
            uint2 u; u.x = pkh(v.x, v.y); u.y = pkh(v.z, v.w);
            *(uint2*)&ku[((size_t)hh * LWMAX + w) * HD + d4] = u;
        } else if (w >= Lw) {
            uint2 u; u.x = 0u; u.y = 0u;
            *(uint2*)&ku[((size_t)hh * LWMAX + w) * HD + d4] = u;
        }
        float4 vv = make_float4(0.f, 0.f, 0.f, 0.f);
        if (w < cnw)     vv = *(const float4*)&vcache[((size_t)(ws + w) * NH + hh) * HD + d4];
        else if (w < Lw) vv = *(const float4*)&vnew[(size_t)(w - cnw) * DIM + hh * HD + d4];
        uint2 u; u.x = pkh(vv.x, vv.y); u.y = pkh(vv.z, vv.w);
        *(uint2*)&vu[((size_t)hh * LWMAX + w) * HD + d4] = u;
    }
}

// ---------------------------------------------------------------------------
// fp16 flash attention — R10 exact (best known): 64 q-rows, 128 threads,
// occ 2, double-buffered cp.async, fixed-shift softmax, P in registers.
// ---------------------------------------------------------------------------
__device__ __forceinline__ void attn_stage(
    const __half* __restrict__ ksrc, const __half* __restrict__ vsrc,
    uint32_t kw, uint32_t vw, int kb, int t)
{
#pragma unroll
    for (int i = 0; i < 8; i++) {
        const int id = t + i * 128;
        const int r = id >> 4, c = id & 15;
        cp16(kw + (uint32_t)(r * ASTR + c * 8) * 2, ksrc + (size_t)(kb + r) * HD + c * 8);
        cp16(vw + (uint32_t)(r * ASTR + c * 8) * 2, vsrc + (size_t)(kb + r) * HD + c * 8);
    }
    CP_COMMIT();
}

__global__ __launch_bounds__(128, 2) void attn_h16(
    const __half* __restrict__ q16,
    const __half* __restrict__ ku, const __half* __restrict__ vu,
    __half* __restrict__ o16,
    const int* __restrict__ cur_start_p, int S)
{
    extern __shared__ __half sma[];
    const int hh = blockIdx.y;
    const int q0 = blockIdx.x * 64;
    const int t = threadIdx.x, l = t & 31, wid = t >> 5;
    const int g = l >> 2, tg = l & 3;

    const int cur = cur_start_p[0];
    const int cur_end = cur + S;
    int ws = cur_end - MAX_ATTN_W; if (ws < 0) ws = 0;
    const int Lw = cur_end - ws;
    const int ntiles = (Lw + 63) >> 6;

    const __half* ksrc = ku + (size_t)hh * LWMAX * HD;
    const __half* vsrc = vu + (size_t)hh * LWMAX * HD;

    const uint32_t sb = smem_u32(sma);
    const uint32_t kwb[2] = { sb, sb + ABUF * 2u };
    const uint32_t vwb[2] = { sb + 2u * ABUF * 2u, sb + 3u * ABUF * 2u };

    const int k_row = (l & 7) + ((l >> 4) & 1) * 8;
    const int k_half = ((l >> 3) & 1) * 8;
    const int v_row = (l & 7) + ((l >> 3) & 1) * 8;
    const int v_dim = ((l >> 4) & 1) * 8;

    // Q A-fragments (already fp16 in natural layout)
    const int row0 = q0 + wid * 16 + g;
    const bool r0ok = row0 < S, r1ok = (row0 + 8) < S;
    uint32_t qa[8][4];
    {
        const uint32_t* qp0 = (const uint32_t*)(q16 + (size_t)(r0ok ? row0 : 0) * DIM + hh * HD);
        const uint32_t* qp1 = (const uint32_t*)(q16 + (size_t)(r1ok ? row0 + 8 : 0) * DIM + hh * HD);
#pragma unroll
        for (int ks = 0; ks < 8; ks++) {
            qa[ks][0] = r0ok ? qp0[8 * ks + tg]     : 0u;
            qa[ks][1] = r1ok ? qp1[8 * ks + tg]     : 0u;
            qa[ks][2] = r0ok ? qp0[8 * ks + tg + 4] : 0u;
            qa[ks][3] = r1ok ? qp1[8 * ks + tg + 4] : 0u;
        }
    }

    float o_acc[16][4];
#pragma unroll
    for (int nt = 0; nt < 16; nt++)
#pragma unroll
        for (int c = 0; c < 4; c++) o_acc[nt][c] = 0.0f;
    float lA = 0.0f, lB = 0.0f;
    const float sc = 0.08838834764831845f;

    attn_stage(ksrc, vsrc, kwb[0], vwb[0], 0, t);

    for (int tile = 0; tile < ntiles; tile++) {
        const int b = tile & 1;
        if (tile + 1 < ntiles) {
            attn_stage(ksrc, vsrc, kwb[1 - b], vwb[1 - b], (tile + 1) * 64, t);
            CP_WAIT(1);
        } else {
            CP_WAIT(0);
        }
        __syncthreads();

        const uint32_t ksb = kwb[b], vsb = vwb[b];

        // S = Q K^T
        float s_acc[8][4];
#pragma unroll
        for (int nt = 0; nt < 8; nt++)
#pragma unroll
            for (int c = 0; c < 4; c++) s_acc[nt][c] = 0.0f;
#pragma unroll
        for (int ks = 0; ks < 8; ks++) {
#pragma unroll
            for (int j = 0; j < 4; j++) {
                uint32_t b0, b1, b2, b3;
                ldsm4(b0, b1, b2, b3,
                      ksb + (uint32_t)((16 * j + k_row) * ASTR + 16 * ks + k_half) * 2);
                mma16(s_acc[2 * j],     qa[ks], b0, b1);
                mma16(s_acc[2 * j + 1], qa[ks], b2, b3);
            }
        }

        // fixed-shift softmax: p = exp(s*sc - SHIFT); masked cols -> 0
        const int kb = tile * 64;
#pragma unroll
        for (int nt = 0; nt < 8; nt++) {
            const int key0 = kb + nt * 8 + 2 * tg;
            const bool ok0 = key0 < Lw, ok1 = (key0 + 1) < Lw;
            const float p0 = ok0 ? __expf(s_acc[nt][0] * sc - SOFTMAX_SHIFT) : 0.0f;
            const float p1 = ok1 ? __expf(s_acc[nt][1] * sc - SOFTMAX_SHIFT) : 0.0f;
            const float p2 = ok0 ? __expf(s_acc[nt][2] * sc - SOFTMAX_SHIFT) : 0.0f;
            const float p3 = ok1 ? __expf(s_acc[nt][3] * sc - SOFTMAX_SHIFT) : 0.0f;
            s_acc[nt][0] = p0; s_acc[nt][1] = p1;
            s_acc[nt][2] = p2; s_acc[nt][3] = p3;
            lA += p0 + p1;
            lB += p2 + p3;
        }

        // O += P V  (A-fragments from registers)
#pragma unroll
        for (int ks = 0; ks < 4; ks++) {
            uint32_t ap[4];
            ap[0] = pkh(s_acc[2 * ks][0],     s_acc[2 * ks][1]);
            ap[1] = pkh(s_acc[2 * ks][2],     s_acc[2 * ks][3]);
            ap[2] = pkh(s_acc[2 * ks + 1][0], s_acc[2 * ks + 1][1]);
            ap[3] = pkh(s_acc[2 * ks + 1][2], s_acc[2 * ks + 1][3]);
#pragma unroll
            for (int j = 0; j < 8; j++) {
                uint32_t b0, b1, b2, b3;
                ldsm4t(b0, b1, b2, b3,
                       vsb + (uint32_t)((16 * ks + v_row) * ASTR + 16 * j + v_dim) * 2);
                mma16(o_acc[2 * j],     ap, b0, b1);
                mma16(o_acc[2 * j + 1], ap, b2, b3);
            }
        }
        __syncthreads();
    }

    // single row-sum reduction at the end (4 lanes share a row)
    lA += __shfl_xor_sync(0xffffffffu, lA, 1);
    lA += __shfl_xor_sync(0xffffffffu, lA, 2);
    lB += __shfl_xor_sync(0xffffffffu, lB, 1);
    lB += __shfl_xor_sync(0xffffffffu, lB, 2);

    const float iA = 1.0f / lA, iB = 1.0f / lB;
#pragma unroll
    for (int nt = 0; nt < 16; nt++) {
        const int cc = hh * HD + nt * 8 + 2 * tg;
        if (r0ok)
            *(uint32_t*)&o16[(size_t)row0 * DIM + cc] = pkh(o_acc[nt][0] * iA, o_acc[nt][1] * iA);
        if (r1ok)
            *(uint32_t*)&o16[(size_t)(row0 + 8) * DIM + cc] = pkh(o_acc[nt][2] * iB, o_acc[nt][3] * iB);
    }
}

// ---------------------------------------------------------------------------
extern "C" void kernel_launch(void* const* d_in, const int* in_sizes, int n_in,
                              void* d_out, int out_size)
{
    const float* x      = (const float*)d_in[0];
    const float* freqs  = (const float*)d_in[1];
    const float* wq     = (const float*)d_in[2];
    const float* bq     = (const float*)d_in[3];
    const float* wk     = (const float*)d_in[4];
    const float* bk     = (const float*)d_in[5];
    const float* wv     = (const float*)d_in[6];
    const float* bv     = (const float*)d_in[7];
    const float* wo     = (const float*)d_in[8];
    const float* bo     = (const float*)d_in[9];
    const float* gq     = (const float*)d_in[10];
    const float* gk     = (const float*)d_in[11];
    const float* kcache = (const float*)d_in[12];
    const float* vcache = (const float*)d_in[13];
    const int* grid_sizes = (const int*)d_in[14];
    const int* cur_start  = (const int*)d_in[16];

    const int S = in_sizes[0] / DIM;

    float *q, *k, *v;
    __half *x16, *q16, *o16, *wq16, *wk16, *wv16, *wo16, *ku, *vu;
    cudaGetSymbolAddress((void**)&q, g_q);
    cudaGetSymbolAddress((void**)&k, g_k);
    cudaGetSymbolAddress((void**)&v, g_v);
    cudaGetSymbolAddress((void**)&x16, g_x16);
    cudaGetSymbolAddress((void**)&q16, g_q16);
    cudaGetSymbolAddress((void**)&o16, g_o16);
    cudaGetSymbolAddress((void**)&wq16, g_wq16);
    cudaGetSymbolAddress((void**)&wk16, g_wk16);
    cudaGetSymbolAddress((void**)&wv16, g_wv16);
    cudaGetSymbolAddress((void**)&wo16, g_wo16);
    cudaGetSymbolAddress((void**)&ku, g_ku);
    cudaGetSymbolAddress((void**)&vu, g_vu);

    const int wn4 = DIM * DIM / 4;
    const int xn4 = S * DIM / 4;
    const int cvb = ((xn4 > wn4 ? xn4 : wn4) + 255) / 256;
    cvt16_all<<<dim3(cvb, 5), 256>>>(x, x16, xn4, wq, wq16, wk, wk16, wv, wv16, wo, wo16, wn4);

    // fused QKV projections — BM=192 variant (324 CTAs ~ single wave)
    const int g192smem = 2 * 12800 * 2;   // 51200 B
    cudaFuncSetAttribute(gemm192_h16, cudaFuncAttributeMaxDynamicSharedMemorySize, g192smem);
    gemm192_h16<<<dim3((S + 191) / 192, DIM / 128, 3), 256, g192smem>>>(
        x16, wq16, bq, q, wk16, bk, k, wv16, bv, v, S);

    rmsnorm_rope<<<dim3(S, 2), 256>>>(q, k, q16, ku, gq, gk, freqs, grid_sizes, cur_start, S);
    fill_kv<<<dim3(LWMAX / 64, NH), 256>>>(kcache, vcache, v, ku, vu, cur_start, S);

    const int asmem = 4 * ABUF * 2;   // 69632 B
    cudaFuncSetAttribute(attn_h16, cudaFuncAttributeMaxDynamicSharedMemorySize, asmem);
    attn_h16<<<dim3((S + 63) / 64, NH), 128, asmem>>>(q16, ku, vu, o16, cur_start, S);

    // output projection — BM=128 (single wave already)
    gemm_h16<<<dim3((S + 127) / 128, DIM / 128), 256>>>(o16, wo16, bo, (float*)d_out, S);
}

// round 14
// speedup vs baseline: 1.0058x; 1.0058x over previous
#include <cuda_runtime.h>
#include <cuda_fp16.h>
#include <math.h>
#include <stdint.h>

#define DIM 1536
#define NH 12
#define HD 128
#define MAXS 2048
#define MAX_ATTN_W 32760
#define LWMAX 8192       // max materialized window (tokens)
#define GSTR 40          // GEMM smem row stride (halfs)
#define ASTR 136         // attention smem row stride (halfs)
#define ABUF (64 * ASTR) // one K or V tile buffer (halfs)
#define SOFTMAX_SHIFT 6.0f

__device__ float  g_q[MAXS * DIM];
__device__ float  g_k[MAXS * DIM];
__device__ float  g_v[MAXS * DIM];
__device__ __half g_x16[MAXS * DIM];
__device__ __half g_q16[MAXS * DIM];
__device__ __half g_o16[MAXS * DIM];
__device__ __half g_wq16[DIM * DIM];
__device__ __half g_wk16[DIM * DIM];
__device__ __half g_wv16[DIM * DIM];
__device__ __half g_wo16[DIM * DIM];
__device__ __half g_ku[(size_t)NH * LWMAX * HD];
__device__ __half g_vu[(size_t)NH * LWMAX * HD];

// ---------------------------------------------------------------------------
__device__ __forceinline__ uint32_t smem_u32(const void* p) {
    uint32_t a;
    asm("{ .reg .u64 t; cvta.to.shared.u64 t, %1; cvt.u32.u64 %0, t; }" : "=r"(a) : "l"(p));
    return a;
}
__device__ __forceinline__ uint32_t pkh(float a, float b) {
    __half2 h = __floats2half2_rn(a, b);
    return *(uint32_t*)&h;
}
__device__ __forceinline__ void mma16(float* d, const uint32_t* a, uint32_t b0, uint32_t b1) {
    asm volatile(
        "mma.sync.aligned.m16n8k16.row.col.f32.f16.f16.f32 "
        "{%0,%1,%2,%3},{%4,%5,%6,%7},{%8,%9},{%0,%1,%2,%3};"
        : "+f"(d[0]), "+f"(d[1]), "+f"(d[2]), "+f"(d[3])
        : "r"(a[0]), "r"(a[1]), "r"(a[2]), "r"(a[3]), "r"(b0), "r"(b1));
}
__device__ __forceinline__ void ldsm4(uint32_t& r0, uint32_t& r1, uint32_t& r2, uint32_t& r3,
                                      uint32_t a) {
    asm volatile("ldmatrix.sync.aligned.m8n8.x4.shared.b16 {%0,%1,%2,%3}, [%4];"
                 : "=r"(r0), "=r"(r1), "=r"(r2), "=r"(r3) : "r"(a));
}
__device__ __forceinline__ void ldsm4t(uint32_t& r0, uint32_t& r1, uint32_t& r2, uint32_t& r3,
                                       uint32_t a) {
    asm volatile("ldmatrix.sync.aligned.m8n8.x4.trans.shared.b16 {%0,%1,%2,%3}, [%4];"
                 : "=r"(r0), "=r"(r1), "=r"(r2), "=r"(r3) : "r"(a));
}
__device__ __forceinline__ void cp16(uint32_t dst, const void* src) {
    asm volatile("cp.async.cg.shared.global [%0], [%1], 16;" :: "r"(dst), "l"(src));
}
__device__ __forceinline__ void cp16z(uint32_t dst, const void* src, int sz) {
    asm volatile("cp.async.cg.shared.global [%0], [%1], 16, %2;" :: "r"(dst), "l"(src), "r"(sz));
}
#define CP_COMMIT() asm volatile("cp.async.commit_group;" ::: "memory")
#define CP_WAIT(n)  asm volatile("cp.async.wait_group %0;" :: "n"(n) : "memory")

// ---------------------------------------------------------------------------
// fused fp32 -> fp16 conversion for x + 4 weight matrices (grid.y selects)
// ---------------------------------------------------------------------------
__global__ void cvt16_all(
    const float* __restrict__ x,  __half* __restrict__ x16,  int xn4,
    const float* __restrict__ w0, __half* __restrict__ o0,
    const float* __restrict__ w1, __half* __restrict__ o1,
    const float* __restrict__ w2, __half* __restrict__ o2,
    const float* __restrict__ w3, __half* __restrict__ o3, int wn4)
{
    const float* in; __half* out; int n4;
    switch (blockIdx.y) {
        case 0: in = x;  out = x16; n4 = xn4; break;
        case 1: in = w0; out = o0;  n4 = wn4; break;
        case 2: in = w1; out = o1;  n4 = wn4; break;
        case 3: in = w2; out = o2;  n4 = wn4; break;
        default: in = w3; out = o3; n4 = wn4; break;
    }
    int i = blockIdx.x * blockDim.x + threadIdx.x;
    if (i < n4) {
        float4 v = ((const float4*)in)[i];
        ((__half2*)out)[2 * i]     = __floats2half2_rn(v.x, v.y);
        ((__half2*)out)[2 * i + 1] = __floats2half2_rn(v.z, v.w);
    }
}

// ---------------------------------------------------------------------------
// fp16 GEMM (R6-proven): Y = A·Wᵀ + bias.  128x128 tile, BK=32, cp.async
// double-buffered, 256 threads, warp 32x64, static smem, lb(256,2).
// ---------------------------------------------------------------------------
__device__ __forceinline__ void gemm_stage(
    const __half* __restrict__ A, const __half* __restrict__ W,
    uint32_t sa, uint32_t sw, int kc, int m0, int n0, int M, int t)
{
#pragma unroll
    for (int i = 0; i < 2; i++) {
        const int id = t + i * 256;
        const int row = id >> 2, slot = id & 3;
        const int ar = m0 + row;
        const __half* asrc = A + (size_t)(ar < M ? ar : 0) * DIM + kc * 32 + slot * 8;
        cp16z(sa + (uint32_t)(row * GSTR + slot * 8) * 2, asrc, ar < M ? 16 : 0);
        cp16(sw + (uint32_t)(row * GSTR + slot * 8) * 2,
             W + (size_t)(n0 + row) * DIM + kc * 32 + slot * 8);
    }
    CP_COMMIT();
}

__global__ __launch_bounds__(256, 2) void gemm_h16(
    const __half* __restrict__ A,
    const __half* __restrict__ W0, const float* __restrict__ B0, float* __restrict__ Y0,
    const __half* __restrict__ W1, const float* __restrict__ B1, float* __restrict__ Y1,
    const __half* __restrict__ W2, const float* __restrict__ B2, float* __restrict__ Y2,
    int M)
{
    __shared__ __half SA[2][128 * GSTR];
    __shared__ __half SW[2][128 * GSTR];

    const __half* W; const float* Bi; float* Y;
    if (blockIdx.z == 0)      { W = W0; Bi = B0; Y = Y0; }
    else if (blockIdx.z == 1) { W = W1; Bi = B1; Y = Y1; }
    else                      { W = W2; Bi = B2; Y = Y2; }

    const int t = threadIdx.x, l = t & 31, wid = t >> 5;
    const int wm = (wid & 3) * 32, wn = (wid >> 2) * 64;
    const int g = l >> 2, tg = l & 3;
    const int m0 = blockIdx.x * 128, n0 = blockIdx.y * 128;

    const uint32_t saw[2] = { smem_u32(SA[0]), smem_u32(SA[1]) };
    const uint32_t sww[2] = { smem_u32(SW[0]), smem_u32(SW[1]) };

    const int a_row = (l & 7) + 8 * ((l >> 3) & 1);
    const int a_half = 8 * ((l >> 4) & 1);
    const int b_row = (l & 7) + 8 * ((l >> 4) & 1);
    const int b_half = 8 * ((l >> 3) & 1);

    float acc[2][8][4];
#pragma unroll
    for (int i = 0; i < 2; i++)
#pragma unroll
        for (int j = 0; j < 8; j++)
#pragma unroll
            for (int c = 0; c < 4; c++) acc[i][j][c] = 0.0f;

    gemm_stage(A, W, saw[0], sww[0], 0, m0, n0, M, t);

    for (int kc = 0; kc < DIM / 32; kc++) {
        const int b = kc & 1;
        if (kc + 1 < DIM / 32) {
            gemm_stage(A, W, saw[1 - b], sww[1 - b], kc + 1, m0, n0, M, t);
            CP_WAIT(1);
        } else {
            CP_WAIT(0);
        }
        __syncthreads();

        const uint32_t ab = saw[b], wb = sww[b];
#pragma unroll
        for (int ks = 0; ks < 2; ks++) {
            uint32_t af[2][4];
            ldsm4(af[0][0], af[0][1], af[0][2], af[0][3],
                  ab + (uint32_t)((wm + a_row) * GSTR + 16 * ks + a_half) * 2);
            ldsm4(af[1][0], af[1][1], af[1][2], af[1][3],
                  ab + (uint32_t)((wm + 16 + a_row) * GSTR + 16 * ks + a_half) * 2);
#pragma unroll
            for (int j = 0; j < 4; j++) {
                uint32_t b0, b1, b2, b3;
                ldsm4(b0, b1, b2, b3,
                      wb + (uint32_t)((wn + 16 * j + b_row) * GSTR + 16 * ks + b_half) * 2);
                mma16(acc[0][2 * j],     af[0], b0, b1);
                mma16(acc[0][2 * j + 1], af[0], b2, b3);
                mma16(acc[1][2 * j],     af[1], b0, b1);
                mma16(acc[1][2 * j + 1], af[1], b2, b3);
            }
        }
        __syncthreads();
    }

#pragma unroll
    for (int mt = 0; mt < 2; mt++) {
        const int r0 = m0 + wm + mt * 16 + g;
#pragma unroll
        for (int nt = 0; nt < 8; nt++) {
            const int cc = n0 + wn + nt * 8 + 2 * tg;
            const float b0 = Bi[cc], b1 = Bi[cc + 1];
            if (r0 < M) {
                float2 v = make_float2(acc[mt][nt][0] + b0, acc[mt][nt][1] + b1);
                *(float2*)&Y[(size_t)r0 * DIM + cc] = v;
            }
            if (r0 + 8 < M) {
                float2 v = make_float2(acc[mt][nt][2] + b0, acc[mt][nt][3] + b1);
                *(float2*)&Y[(size_t)(r0 + 8) * DIM + cc] = v;
            }
        }
    }
}

// ---------------------------------------------------------------------------
// RMSNorm + RoPE.  q: fp16 into q16 (natural layout).
// k: fp16 into Ku[head][cnw+s][dim].
// ---------------------------------------------------------------------------
__global__ __launch_bounds__(256) void rmsnorm_rope(
    const float* __restrict__ q, const float* __restrict__ k,
    __half* __restrict__ q16, __half* __restrict__ ku,
    const float* __restrict__ gq, const float* __restrict__ gk,
    const float* __restrict__ freqs,
    const int* __restrict__ grid_sizes,
    const int* __restrict__ cur_start_p, int S)
{
    const int s = blockIdx.x;
    const int which = blockIdx.y;
    const float* row = (which ? k : q) + (size_t)s * DIM;
    const float* g = which ? gk : gq;

    __shared__ float red[8];
    __shared__ float cs[64], sn[64];
    const int t = threadIdx.x;

    float ss = 0.0f;
#pragma unroll
    for (int i = 0; i < 6; i++) {
        const float v = row[t + i * 256];
        ss += v * v;
    }
#pragma unroll
    for (int o = 16; o; o >>= 1) ss += __shfl_xor_sync(0xffffffffu, ss, o);
    if ((t & 31) == 0) red[t >> 5] = ss;
    __syncthreads();
    if (t < 8) {
        float v = red[t];
#pragma unroll
        for (int o = 4; o; o >>= 1) v += __shfl_xor_sync(0xffu, v, o);
        if (t == 0) red[0] = v;
    }

    const int Hh = grid_sizes[1];
    const int Ww = grid_sizes[2];
    const int FHW = grid_sizes[0] * Hh * Ww;
    const bool rot = (s < FHW);
    const int cur = cur_start_p[0];
    int ws = cur + S - MAX_ATTN_W; if (ws < 0) ws = 0;
    const int cnw = cur - ws;

    if (rot && t < 64) {
        const int fs = Hh * Ww;
        const int sf = cur / fs;
        const int f = s / fs;
        const int rem = s - f * fs;
        const int h = rem / Ww;
        const int w = rem - h * Ww;
        int idx;
        if (t < 22)       idx = sf + f;
        else if (t < 43)  idx = h;
        else              idx = w;
        const float ang = freqs[idx * 64 + t];
        cs[t] = cosf(ang);
        sn[t] = sinf(ang);
    }
    __syncthreads();

    const float scale = rsqrtf(red[0] * (1.0f / DIM) + 1e-6f);

#pragma unroll
    for (int r = 0; r < 3; r++) {
        const int p = t + r * 256;
        const int j = p & 63;
        const int e0 = 2 * p, e1 = e0 + 1;
        const float a = row[e0] * scale * g[e0];
        const float b = row[e1] * scale * g[e1];
        float o0, o1;
        if (rot) {
            const float c = cs[j], s_ = sn[j];
            o0 = a * c - b * s_;
            o1 = a * s_ + b * c;
        } else {
            o0 = a; o1 = b;
        }
        const uint32_t hv = pkh(o0, o1);
        if (which == 0) {
            *(uint32_t*)&q16[(size_t)s * DIM + e0] = hv;
        } else {
            const int hh = e0 >> 7, d = e0 & 127;
            *(uint32_t*)&ku[((size_t)hh * LWMAX + cnw + s) * HD + d] = hv;
        }
    }
}

// ---------------------------------------------------------------------------
// Materialize fp16 window KV (cache part + pad; V also new part).
// ---------------------------------------------------------------------------
__global__ __launch_bounds__(256) void fill_kv(
    const float* __restrict__ kcache, const float* __restrict__ vcache,
    const float* __restrict__ vnew,
    __half* __restrict__ ku, __half* __restrict__ vu,
    const int* __restrict__ cur_start_p, int S)
{
    const int hh = blockIdx.y;
    const int wt = blockIdx.x;
    const int t = threadIdx.x;

    const int cur = cur_start_p[0];
    int ws = cur + S - MAX_ATTN_W; if (ws < 0) ws = 0;
    const int cnw = cur - ws;
    const int Lw = cur + S - ws;
    const int Lpad = (Lw + 63) & ~63;
    if (wt * 64 >= Lpad) return;

#pragma unroll
    for (int i = 0; i < 8; i++) {
        const int idx = t + i * 256;
        const int tok = idx >> 5;
        const int d4 = (idx & 31) * 4;
        const int w = wt * 64 + tok;

        if (w < cnw) {
            const float4 v = *(const float4*)&kcache[((size_t)(ws + w) * NH + hh) * HD + d4];
            uint2 u; u.x = pkh(v.x, v.y); u.y = pkh(v.z, v.w);
            *(uint2*)&ku[((size_t)hh * LWMAX + w) * HD + d4] = u;
        } else if (w >= Lw) {
            uint2 u; u.x = 0u; u.y = 0u;
            *(uint2*)&ku[((size_t)hh * LWMAX + w) * HD + d4] = u;
        }
        float4 vv = make_float4(0.f, 0.f, 0.f, 0.f);
        if (w < cnw)     vv = *(const float4*)&vcache[((size_t)(ws + w) * NH + hh) * HD + d4];
        else if (w < Lw) vv = *(const float4*)&vnew[(size_t)(w - cnw) * DIM + hh * HD + d4];
        uint2 u; u.x = pkh(vv.x, vv.y); u.y = pkh(vv.z, vv.w);
        *(uint2*)&vu[((size_t)hh * LWMAX + w) * HD + d4] = u;
    }
}

// ---------------------------------------------------------------------------
// fp16 flash attention — R10 exact, but occupancy 3 (lb(128,3)):
// 12 warps/SM (3/SMSP) for latency hiding + grid 300 <= 444 -> single wave.
// Fixed-shift softmax keeps live regs ~150 < 170-reg occ-3 cap.
// ---------------------------------------------------------------------------
__device__ __forceinline__ void attn_stage(
    const __half* __restrict__ ksrc, const __half* __restrict__ vsrc,
    uint32_t kw, uint32_t vw, int kb, int t)
{
#pragma unroll
    for (int i = 0; i < 8; i++) {
        const int id = t + i * 128;
        const int r = id >> 4, c = id & 15;
        cp16(kw + (uint32_t)(r * ASTR + c * 8) * 2, ksrc + (size_t)(kb + r) * HD + c * 8);
        cp16(vw + (uint32_t)(r * ASTR + c * 8) * 2, vsrc + (size_t)(kb + r) * HD + c * 8);
    }
    CP_COMMIT();
}

__global__ __launch_bounds__(128, 3) void attn_h16(
    const __half* __restrict__ q16,
    const __half* __restrict__ ku, const __half* __restrict__ vu,
    __half* __restrict__ o16,
    const int* __restrict__ cur_start_p, int S)
{
    extern __shared__ __half sma[];
    const int hh = blockIdx.y;
    const int q0 = blockIdx.x * 64;
    const int t = threadIdx.x, l = t & 31, wid = t >> 5;
    const int g = l >> 2, tg = l & 3;

    const int cur = cur_start_p[0];
    const int cur_end = cur + S;
    int ws = cur_end - MAX_ATTN_W; if (ws < 0) ws = 0;
    const int Lw = cur_end - ws;
    const int ntiles = (Lw + 63) >> 6;

    const __half* ksrc = ku + (size_t)hh * LWMAX * HD;
    const __half* vsrc = vu + (size_t)hh * LWMAX * HD;

    const uint32_t sb = smem_u32(sma);
    const uint32_t kwb[2] = { sb, sb + ABUF * 2u };
    const uint32_t vwb[2] = { sb + 2u * ABUF * 2u, sb + 3u * ABUF * 2u };

    const int k_row = (l & 7) + ((l >> 4) & 1) * 8;
    const int k_half = ((l >> 3) & 1) * 8;
    const int v_row = (l & 7) + ((l >> 3) & 1) * 8;
    const int v_dim = ((l >> 4) & 1) * 8;

    // Q A-fragments (already fp16 in natural layout)
    const int row0 = q0 + wid * 16 + g;
    const bool r0ok = row0 < S, r1ok = (row0 + 8) < S;
    uint32_t qa[8][4];
    {
        const uint32_t* qp0 = (const uint32_t*)(q16 + (size_t)(r0ok ? row0 : 0) * DIM + hh * HD);
        const uint32_t* qp1 = (const uint32_t*)(q16 + (size_t)(r1ok ? row0 + 8 : 0) * DIM + hh * HD);
#pragma unroll
        for (int ks = 0; ks < 8; ks++) {
            qa[ks][0] = r0ok ? qp0[8 * ks + tg]     : 0u;
            qa[ks][1] = r1ok ? qp1[8 * ks + tg]     : 0u;
            qa[ks][2] = r0ok ? qp0[8 * ks + tg + 4] : 0u;
            qa[ks][3] = r1ok ? qp1[8 * ks + tg + 4] : 0u;
        }
    }

    float o_acc[16][4];
#pragma unroll
    for (int nt = 0; nt < 16; nt++)
#pragma unroll
        for (int c = 0; c < 4; c++) o_acc[nt][c] = 0.0f;
    float lA = 0.0f, lB = 0.0f;
    const float sc = 0.08838834764831845f;

    attn_stage(ksrc, vsrc, kwb[0], vwb[0], 0, t);

    for (int tile = 0; tile < ntiles; tile++) {
        const int b = tile & 1;
        if (tile + 1 < ntiles) {
            attn_stage(ksrc, vsrc, kwb[1 - b], vwb[1 - b], (tile + 1) * 64, t);
            CP_WAIT(1);
        } else {
            CP_WAIT(0);
        }
        __syncthreads();

        const uint32_t ksb = kwb[b], vsb = vwb[b];

        // S = Q K^T
        float s_acc[8][4];
#pragma unroll
        for (int nt = 0; nt < 8; nt++)
#pragma unroll
            for (int c = 0; c < 4; c++) s_acc[nt][c] = 0.0f;
#pragma unroll
        for (int ks = 0; ks < 8; ks++) {
#pragma unroll
            for (int j = 0; j < 4; j++) {
                uint32_t b0, b1, b2, b3;
                ldsm4(b0, b1, b2, b3,
                      ksb + (uint32_t)((16 * j + k_row) * ASTR + 16 * ks + k_half) * 2);
                mma16(s_acc[2 * j],     qa[ks], b0, b1);
                mma16(s_acc[2 * j + 1], qa[ks], b2, b3);
            }
        }

        // fixed-shift softmax: p = exp(s*sc - SHIFT); masked cols -> 0
        const int kb = tile * 64;
#pragma unroll
        for (int nt = 0; nt < 8; nt++) {
            const int key0 = kb + nt * 8 + 2 * tg;
            const bool ok0 = key0 < Lw, ok1 = (key0 + 1) < Lw;
            const float p0 = ok0 ? __expf(s_acc[nt][0] * sc - SOFTMAX_SHIFT) : 0.0f;
            const float p1 = ok1 ? __expf(s_acc[nt][1] * sc - SOFTMAX_SHIFT) : 0.0f;
            const float p2 = ok0 ? __expf(s_acc[nt][2] * sc - SOFTMAX_SHIFT) : 0.0f;
            const float p3 = ok1 ? __expf(s_acc[nt][3] * sc - SOFTMAX_SHIFT) : 0.0f;
            s_acc[nt][0] = p0; s_acc[nt][1] = p1;
            s_acc[nt][2] = p2; s_acc[nt][3] = p3;
            lA += p0 + p1;
            lB += p2 + p3;
        }

        // O += P V  (A-fragments from registers)
#pragma unroll
        for (int ks = 0; ks < 4; ks++) {
            uint32_t ap[4];
            ap[0] = pkh(s_acc[2 * ks][0],     s_acc[2 * ks][1]);
            ap[1] = pkh(s_acc[2 * ks][2],     s_acc[2 * ks][3]);
            ap[2] = pkh(s_acc[2 * ks + 1][0], s_acc[2 * ks + 1][1]);
            ap[3] = pkh(s_acc[2 * ks + 1][2], s_acc[2 * ks + 1][3]);
#pragma unroll
            for (int j = 0; j < 8; j++) {
                uint32_t b0, b1, b2, b3;
                ldsm4t(b0, b1, b2, b3,
                       vsb + (uint32_t)((16 * ks + v_row) * ASTR + 16 * j + v_dim) * 2);
                mma16(o_acc[2 * j],     ap, b0, b1);
                mma16(o_acc[2 * j + 1], ap, b2, b3);
            }
        }
        __syncthreads();
    }

    // single row-sum reduction at the end (4 lanes share a row)
    lA += __shfl_xor_sync(0xffffffffu, lA, 1);
    lA += __shfl_xor_sync(0xffffffffu, lA, 2);
    lB += __shfl_xor_sync(0xffffffffu, lB, 1);
    lB += __shfl_xor_sync(0xffffffffu, lB, 2);

    const float iA = 1.0f / lA, iB = 1.0f / lB;
#pragma unroll
    for (int nt = 0; nt < 16; nt++) {
        const int cc = hh * HD + nt * 8 + 2 * tg;
        if (r0ok)
            *(uint32_t*)&o16[(size_t)row0 * DIM + cc] = pkh(o_acc[nt][0] * iA, o_acc[nt][1] * iA);
        if (r1ok)
            *(uint32_t*)&o16[(size_t)(row0 + 8) * DIM + cc] = pkh(o_acc[nt][2] * iB, o_acc[nt][3] * iB);
    }
}

// ---------------------------------------------------------------------------
extern "C" void kernel_launch(void* const* d_in, const int* in_sizes, int n_in,
                              void* d_out, int out_size)
{
    const float* x      = (const float*)d_in[0];
    const float* freqs  = (const float*)d_in[1];
    const float* wq     = (const float*)d_in[2];
    const float* bq     = (const float*)d_in[3];
    const float* wk     = (const float*)d_in[4];
    const float* bk     = (const float*)d_in[5];
    const float* wv     = (const float*)d_in[6];
    const float* bv     = (const float*)d_in[7];
    const float* wo     = (const float*)d_in[8];
    const float* bo     = (const float*)d_in[9];
    const float* gq     = (const float*)d_in[10];
    const float* gk     = (const float*)d_in[11];
    const float* kcache = (const float*)d_in[12];
    const float* vcache = (const float*)d_in[13];
    const int* grid_sizes = (const int*)d_in[14];
    const int* cur_start  = (const int*)d_in[16];

    const int S = in_sizes[0] / DIM;

    float *q, *k, *v;
    __half *x16, *q16, *o16, *wq16, *wk16, *wv16, *wo16, *ku, *vu;
    cudaGetSymbolAddress((void**)&q, g_q);
    cudaGetSymbolAddress((void**)&k, g_k);
    cudaGetSymbolAddress((void**)&v, g_v);
    cudaGetSymbolAddress((void**)&x16, g_x16);
    cudaGetSymbolAddress((void**)&q16, g_q16);
    cudaGetSymbolAddress((void**)&o16, g_o16);
    cudaGetSymbolAddress((void**)&wq16, g_wq16);
    cudaGetSymbolAddress((void**)&wk16, g_wk16);
    cudaGetSymbolAddress((void**)&wv16, g_wv16);
    cudaGetSymbolAddress((void**)&wo16, g_wo16);
    cudaGetSymbolAddress((void**)&ku, g_ku);
    cudaGetSymbolAddress((void**)&vu, g_vu);

    const int wn4 = DIM * DIM / 4;
    const int xn4 = S * DIM / 4;
    const int cvb = ((xn4 > wn4 ? xn4 : wn4) + 255) / 256;
    cvt16_all<<<dim3(cvb, 5), 256>>>(x, x16, xn4, wq, wq16, wk, wk16, wv, wv16, wo, wo16, wn4);

    // fused QKV projections
    gemm_h16<<<dim3((S + 127) / 128, DIM / 128, 3), 256>>>(
        x16, wq16, bq, q, wk16, bk, k, wv16, bv, v, S);

    rmsnorm_rope<<<dim3(S, 2), 256>>>(q, k, q16, ku, gq, gk, freqs, grid_sizes, cur_start, S);
    fill_kv<<<dim3(LWMAX / 64, NH), 256>>>(kcache, vcache, v, ku, vu, cur_start, S);

    const int asmem = 4 * ABUF * 2;   // 69632 B
    cudaFuncSetAttribute(attn_h16, cudaFuncAttributeMaxDynamicSharedMemorySize, asmem);
    attn_h16<<<dim3((S + 63) / 64, NH), 128, asmem>>>(q16, ku, vu, o16, cur_start, S);

    // output projection
    gemm_h16<<<dim3((S + 127) / 128, DIM / 128, 1), 256>>>(
        o16, wo16, bo, (float*)d_out, wo16, bo, (float*)d_out, wo16, bo, (float*)d_out, S);
}

// round 15
// speedup vs baseline: 1.1572x; 1.1505x over previous
#include <cuda_runtime.h>
#include <cuda_fp16.h>
#include <math.h>
#include <stdint.h>

#define DIM 1536
#define NH 12
#define HD 128
#define MAXS 2048
#define MAX_ATTN_W 32760
#define LWMAX 8192       // max materialized window (tokens)
#define GSTR 40          // GEMM smem row stride (halfs)
#define ASTR 136         // attention smem row stride (halfs)
#define ABUF (64 * ASTR) // one K or V tile buffer (halfs)
#define SOFTMAX_SHIFT 6.0f
#define FILLB (LWMAX / 64 * NH)   // 1536 fill blocks

__device__ float  g_q[MAXS * DIM];
__device__ float  g_k[MAXS * DIM];
__device__ float  g_v[MAXS * DIM];
__device__ __half g_x16[MAXS * DIM];
__device__ __half g_q16[MAXS * DIM];
__device__ __half g_o16[MAXS * DIM];
__device__ __half g_wq16[DIM * DIM];
__device__ __half g_wk16[DIM * DIM];
__device__ __half g_wv16[DIM * DIM];
__device__ __half g_wo16[DIM * DIM];
__device__ __half g_ku[(size_t)NH * LWMAX * HD];
__device__ __half g_vu[(size_t)NH * LWMAX * HD];

// ---------------------------------------------------------------------------
__device__ __forceinline__ uint32_t smem_u32(const void* p) {
    uint32_t a;
    asm("{ .reg .u64 t; cvta.to.shared.u64 t, %1; cvt.u32.u64 %0, t; }" : "=r"(a) : "l"(p));
    return a;
}
__device__ __forceinline__ uint32_t pkh(float a, float b) {
    __half2 h = __floats2half2_rn(a, b);
    return *(uint32_t*)&h;
}
__device__ __forceinline__ void mma16(float* d, const uint32_t* a, uint32_t b0, uint32_t b1) {
    asm volatile(
        "mma.sync.aligned.m16n8k16.row.col.f32.f16.f16.f32 "
        "{%0,%1,%2,%3},{%4,%5,%6,%7},{%8,%9},{%0,%1,%2,%3};"
        : "+f"(d[0]), "+f"(d[1]), "+f"(d[2]), "+f"(d[3])
        : "r"(a[0]), "r"(a[1]), "r"(a[2]), "r"(a[3]), "r"(b0), "r"(b1));
}
__device__ __forceinline__ void ldsm4(uint32_t& r0, uint32_t& r1, uint32_t& r2, uint32_t& r3,
                                      uint32_t a) {
    asm volatile("ldmatrix.sync.aligned.m8n8.x4.shared.b16 {%0,%1,%2,%3}, [%4];"
                 : "=r"(r0), "=r"(r1), "=r"(r2), "=r"(r3) : "r"(a));
}
__device__ __forceinline__ void ldsm4t(uint32_t& r0, uint32_t& r1, uint32_t& r2, uint32_t& r3,
                                       uint32_t a) {
    asm volatile("ldmatrix.sync.aligned.m8n8.x4.trans.shared.b16 {%0,%1,%2,%3}, [%4];"
                 : "=r"(r0), "=r"(r1), "=r"(r2), "=r"(r3) : "r"(a));
}
__device__ __forceinline__ void cp16(uint32_t dst, const void* src) {
    asm volatile("cp.async.cg.shared.global [%0], [%1], 16;" :: "r"(dst), "l"(src));
}
__device__ __forceinline__ void cp16z(uint32_t dst, const void* src, int sz) {
    asm volatile("cp.async.cg.shared.global [%0], [%1], 16, %2;" :: "r"(dst), "l"(src), "r"(sz));
}
#define CP_COMMIT() asm volatile("cp.async.commit_group;" ::: "memory")
#define CP_WAIT(n)  asm volatile("cp.async.wait_group %0;" :: "n"(n) : "memory")

// ---------------------------------------------------------------------------
// fused fp32 -> fp16 conversion for x + 4 weight matrices (grid.y selects)
// ---------------------------------------------------------------------------
__global__ void cvt16_all(
    const float* __restrict__ x,  __half* __restrict__ x16,  int xn4,
    const float* __restrict__ w0, __half* __restrict__ o0,
    const float* __restrict__ w1, __half* __restrict__ o1,
    const float* __restrict__ w2, __half* __restrict__ o2,
    const float* __restrict__ w3, __half* __restrict__ o3, int wn4)
{
    const float* in; __half* out; int n4;
    switch (blockIdx.y) {
        case 0: in = x;  out = x16; n4 = xn4; break;
        case 1: in = w0; out = o0;  n4 = wn4; break;
        case 2: in = w1; out = o1;  n4 = wn4; break;
        case 3: in = w2; out = o2;  n4 = wn4; break;
        default: in = w3; out = o3; n4 = wn4; break;
    }
    int i = blockIdx.x * blockDim.x + threadIdx.x;
    if (i < n4) {
        float4 v = ((const float4*)in)[i];
        ((__half2*)out)[2 * i]     = __floats2half2_rn(v.x, v.y);
        ((__half2*)out)[2 * i + 1] = __floats2half2_rn(v.z, v.w);
    }
}

// ---------------------------------------------------------------------------
// fp16 GEMM (R6-proven): Y = A·Wᵀ + bias.  128x128 tile, BK=32, cp.async
// double-buffered, 256 threads, warp 32x64, static smem, lb(256,2).
// ---------------------------------------------------------------------------
__device__ __forceinline__ void gemm_stage(
    const __half* __restrict__ A, const __half* __restrict__ W,
    uint32_t sa, uint32_t sw, int kc, int m0, int n0, int M, int t)
{
#pragma unroll
    for (int i = 0; i < 2; i++) {
        const int id = t + i * 256;
        const int row = id >> 2, slot = id & 3;
        const int ar = m0 + row;
        const __half* asrc = A + (size_t)(ar < M ? ar : 0) * DIM + kc * 32 + slot * 8;
        cp16z(sa + (uint32_t)(row * GSTR + slot * 8) * 2, asrc, ar < M ? 16 : 0);
        cp16(sw + (uint32_t)(row * GSTR + slot * 8) * 2,
             W + (size_t)(n0 + row) * DIM + kc * 32 + slot * 8);
    }
    CP_COMMIT();
}

__global__ __launch_bounds__(256, 2) void gemm_h16(
    const __half* __restrict__ A,
    const __half* __restrict__ W0, const float* __restrict__ B0, float* __restrict__ Y0,
    const __half* __restrict__ W1, const float* __restrict__ B1, float* __restrict__ Y1,
    const __half* __restrict__ W2, const float* __restrict__ B2, float* __restrict__ Y2,
    int M)
{
    __shared__ __half SA[2][128 * GSTR];
    __shared__ __half SW[2][128 * GSTR];

    const __half* W; const float* Bi; float* Y;
    if (blockIdx.z == 0)      { W = W0; Bi = B0; Y = Y0; }
    else if (blockIdx.z == 1) { W = W1; Bi = B1; Y = Y1; }
    else                      { W = W2; Bi = B2; Y = Y2; }

    const int t = threadIdx.x, l = t & 31, wid = t >> 5;
    const int wm = (wid & 3) * 32, wn = (wid >> 2) * 64;
    const int g = l >> 2, tg = l & 3;
    const int m0 = blockIdx.x * 128, n0 = blockIdx.y * 128;

    const uint32_t saw[2] = { smem_u32(SA[0]), smem_u32(SA[1]) };
    const uint32_t sww[2] = { smem_u32(SW[0]), smem_u32(SW[1]) };

    const int a_row = (l & 7) + 8 * ((l >> 3) & 1);
    const int a_half = 8 * ((l >> 4) & 1);
    const int b_row = (l & 7) + 8 * ((l >> 4) & 1);
    const int b_half = 8 * ((l >> 3) & 1);

    float acc[2][8][4];
#pragma unroll
    for (int i = 0; i < 2; i++)
#pragma unroll
        for (int j = 0; j < 8; j++)
#pragma unroll
            for (int c = 0; c < 4; c++) acc[i][j][c] = 0.0f;

    gemm_stage(A, W, saw[0], sww[0], 0, m0, n0, M, t);

    for (int kc = 0; kc < DIM / 32; kc++) {
        const int b = kc & 1;
        if (kc + 1 < DIM / 32) {
            gemm_stage(A, W, saw[1 - b], sww[1 - b], kc + 1, m0, n0, M, t);
            CP_WAIT(1);
        } else {
            CP_WAIT(0);
        }
        __syncthreads();

        const uint32_t ab = saw[b], wb = sww[b];
#pragma unroll
        for (int ks = 0; ks < 2; ks++) {
            uint32_t af[2][4];
            ldsm4(af[0][0], af[0][1], af[0][2], af[0][3],
                  ab + (uint32_t)((wm + a_row) * GSTR + 16 * ks + a_half) * 2);
            ldsm4(af[1][0], af[1][1], af[1][2], af[1][3],
                  ab + (uint32_t)((wm + 16 + a_row) * GSTR + 16 * ks + a_half) * 2);
#pragma unroll
            for (int j = 0; j < 4; j++) {
                uint32_t b0, b1, b2, b3;
                ldsm4(b0, b1, b2, b3,
                      wb + (uint32_t)((wn + 16 * j + b_row) * GSTR + 16 * ks + b_half) * 2);
                mma16(acc[0][2 * j],     af[0], b0, b1);
                mma16(acc[0][2 * j + 1], af[0], b2, b3);
                mma16(acc[1][2 * j],     af[1], b0, b1);
                mma16(acc[1][2 * j + 1], af[1], b2, b3);
            }
        }
        __syncthreads();
    }

#pragma unroll
    for (int mt = 0; mt < 2; mt++) {
        const int r0 = m0 + wm + mt * 16 + g;
#pragma unroll
        for (int nt = 0; nt < 8; nt++) {
            const int cc = n0 + wn + nt * 8 + 2 * tg;
            const float b0 = Bi[cc], b1 = Bi[cc + 1];
            if (r0 < M) {
                float2 v = make_float2(acc[mt][nt][0] + b0, acc[mt][nt][1] + b1);
                *(float2*)&Y[(size_t)r0 * DIM + cc] = v;
            }
            if (r0 + 8 < M) {
                float2 v = make_float2(acc[mt][nt][2] + b0, acc[mt][nt][3] + b1);
                *(float2*)&Y[(size_t)(r0 + 8) * DIM + cc] = v;
            }
        }
    }
}

// ---------------------------------------------------------------------------
// FUSED aux kernel: blocks [0, 2S) do RMSNorm+RoPE (q -> q16, k -> Ku new
// region); blocks [2S, 2S+FILLB) materialize the KV cache region + pad.
// ---------------------------------------------------------------------------
__global__ __launch_bounds__(256) void rope_fill(
    const float* __restrict__ q, const float* __restrict__ k,
    __half* __restrict__ q16, __half* __restrict__ ku, __half* __restrict__ vu,
    const float* __restrict__ gq, const float* __restrict__ gk,
    const float* __restrict__ freqs,
    const int* __restrict__ grid_sizes,
    const float* __restrict__ kcache, const float* __restrict__ vcache,
    const float* __restrict__ vnew,
    const int* __restrict__ cur_start_p, int S)
{
    const int t = threadIdx.x;
    const int cur = cur_start_p[0];
    int ws = cur + S - MAX_ATTN_W; if (ws < 0) ws = 0;
    const int cnw = cur - ws;
    const int Lw = cur + S - ws;

    if (blockIdx.x >= 2 * (unsigned)S) {
        // ------------------- fill_kv part -------------------
        const int fb = blockIdx.x - 2 * S;
        const int wt = fb & 127;          // FILLB = 128 * NH
        const int hh = fb >> 7;
        const int Lpad = (Lw + 63) & ~63;
        if (wt * 64 >= Lpad) return;

#pragma unroll
        for (int i = 0; i < 8; i++) {
            const int idx = t + i * 256;
            const int tok = idx >> 5;
            const int d4 = (idx & 31) * 4;
            const int w = wt * 64 + tok;

            if (w < cnw) {
                const float4 v = *(const float4*)&kcache[((size_t)(ws + w) * NH + hh) * HD + d4];
                uint2 u; u.x = pkh(v.x, v.y); u.y = pkh(v.z, v.w);
                *(uint2*)&ku[((size_t)hh * LWMAX + w) * HD + d4] = u;
            } else if (w >= Lw) {
                uint2 u; u.x = 0u; u.y = 0u;
                *(uint2*)&ku[((size_t)hh * LWMAX + w) * HD + d4] = u;
            }
            float4 vv = make_float4(0.f, 0.f, 0.f, 0.f);
            if (w < cnw)     vv = *(const float4*)&vcache[((size_t)(ws + w) * NH + hh) * HD + d4];
            else if (w < Lw) vv = *(const float4*)&vnew[(size_t)(w - cnw) * DIM + hh * HD + d4];
            uint2 u; u.x = pkh(vv.x, vv.y); u.y = pkh(vv.z, vv.w);
            *(uint2*)&vu[((size_t)hh * LWMAX + w) * HD + d4] = u;
        }
        return;
    }

    // ------------------- rmsnorm + rope part -------------------
    const int s = blockIdx.x >> 1;
    const int which = blockIdx.x & 1;
    const float* row = (which ? k : q) + (size_t)s * DIM;
    const float* g = which ? gk : gq;

    __shared__ float red[8];
    __shared__ float cs[64], sn[64];

    float ss = 0.0f;
#pragma unroll
    for (int i = 0; i < 6; i++) {
        const float v = row[t + i * 256];
        ss += v * v;
    }
#pragma unroll
    for (int o = 16; o; o >>= 1) ss += __shfl_xor_sync(0xffffffffu, ss, o);
    if ((t & 31) == 0) red[t >> 5] = ss;
    __syncthreads();
    if (t < 8) {
        float v = red[t];
#pragma unroll
        for (int o = 4; o; o >>= 1) v += __shfl_xor_sync(0xffu, v, o);
        if (t == 0) red[0] = v;
    }

    const int Hh = grid_sizes[1];
    const int Ww = grid_sizes[2];
    const int FHW = grid_sizes[0] * Hh * Ww;
    const bool rot = (s < FHW);

    if (rot && t < 64) {
        const int fs = Hh * Ww;
        const int sf = cur / fs;
        const int f = s / fs;
        const int rem = s - f * fs;
        const int h = rem / Ww;
        const int w = rem - h * Ww;
        int idx;
        if (t < 22)       idx = sf + f;
        else if (t < 43)  idx = h;
        else              idx = w;
        const float ang = freqs[idx * 64 + t];
        cs[t] = cosf(ang);
        sn[t] = sinf(ang);
    }
    __syncthreads();

    const float scale = rsqrtf(red[0] * (1.0f / DIM) + 1e-6f);

#pragma unroll
    for (int r = 0; r < 3; r++) {
        const int p = t + r * 256;
        const int j = p & 63;
        const int e0 = 2 * p, e1 = e0 + 1;
        const float a = row[e0] * scale * g[e0];
        const float b = row[e1] * scale * g[e1];
        float o0, o1;
        if (rot) {
            const float c = cs[j], s_ = sn[j];
            o0 = a * c - b * s_;
            o1 = a * s_ + b * c;
        } else {
            o0 = a; o1 = b;
        }
        const uint32_t hv = pkh(o0, o1);
        if (which == 0) {
            *(uint32_t*)&q16[(size_t)s * DIM + e0] = hv;
        } else {
            const int hh = e0 >> 7, d = e0 & 127;
            *(uint32_t*)&ku[((size_t)hh * LWMAX + cnw + s) * HD + d] = hv;
        }
    }
}

// ---------------------------------------------------------------------------
// fp16 flash attention — R10 exact (best known): 64 q-rows, 128 threads,
// occ 2, double-buffered cp.async, fixed-shift softmax, P in registers.
// ---------------------------------------------------------------------------
__device__ __forceinline__ void attn_stage(
    const __half* __restrict__ ksrc, const __half* __restrict__ vsrc,
    uint32_t kw, uint32_t vw, int kb, int t)
{
#pragma unroll
    for (int i = 0; i < 8; i++) {
        const int id = t + i * 128;
        const int r = id >> 4, c = id & 15;
        cp16(kw + (uint32_t)(r * ASTR + c * 8) * 2, ksrc + (size_t)(kb + r) * HD + c * 8);
        cp16(vw + (uint32_t)(r * ASTR + c * 8) * 2, vsrc + (size_t)(kb + r) * HD + c * 8);
    }
    CP_COMMIT();
}

__global__ __launch_bounds__(128, 2) void attn_h16(
    const __half* __restrict__ q16,
    const __half* __restrict__ ku, const __half* __restrict__ vu,
    __half* __restrict__ o16,
    const int* __restrict__ cur_start_p, int S)
{
    extern __shared__ __half sma[];
    const int hh = blockIdx.y;
    const int q0 = blockIdx.x * 64;
    const int t = threadIdx.x, l = t & 31, wid = t >> 5;
    const int g = l >> 2, tg = l & 3;

    const int cur = cur_start_p[0];
    const int cur_end = cur + S;
    int ws = cur_end - MAX_ATTN_W; if (ws < 0) ws = 0;
    const int Lw = cur_end - ws;
    const int ntiles = (Lw + 63) >> 6;

    const __half* ksrc = ku + (size_t)hh * LWMAX * HD;
    const __half* vsrc = vu + (size_t)hh * LWMAX * HD;

    const uint32_t sb = smem_u32(sma);
    const uint32_t kwb[2] = { sb, sb + ABUF * 2u };
    const uint32_t vwb[2] = { sb + 2u * ABUF * 2u, sb + 3u * ABUF * 2u };

    const int k_row = (l & 7) + ((l >> 4) & 1) * 8;
    const int k_half = ((l >> 3) & 1) * 8;
    const int v_row = (l & 7) + ((l >> 3) & 1) * 8;
    const int v_dim = ((l >> 4) & 1) * 8;

    // Q A-fragments (already fp16 in natural layout)
    const int row0 = q0 + wid * 16 + g;
    const bool r0ok = row0 < S, r1ok = (row0 + 8) < S;
    uint32_t qa[8][4];
    {
        const uint32_t* qp0 = (const uint32_t*)(q16 + (size_t)(r0ok ? row0 : 0) * DIM + hh * HD);
        const uint32_t* qp1 = (const uint32_t*)(q16 + (size_t)(r1ok ? row0 + 8 : 0) * DIM + hh * HD);
#pragma unroll
        for (int ks = 0; ks < 8; ks++) {
            qa[ks][0] = r0ok ? qp0[8 * ks + tg]     : 0u;
            qa[ks][1] = r1ok ? qp1[8 * ks + tg]     : 0u;
            qa[ks][2] = r0ok ? qp0[8 * ks + tg + 4] : 0u;
            qa[ks][3] = r1ok ? qp1[8 * ks + tg + 4] : 0u;
        }
    }

    float o_acc[16][4];
#pragma unroll
    for (int nt = 0; nt < 16; nt++)
#pragma unroll
        for (int c = 0; c < 4; c++) o_acc[nt][c] = 0.0f;
    float lA = 0.0f, lB = 0.0f;
    const float sc = 0.08838834764831845f;

    attn_stage(ksrc, vsrc, kwb[0], vwb[0], 0, t);

    for (int tile = 0; tile < ntiles; tile++) {
        const int b = tile & 1;
        if (tile + 1 < ntiles) {
            attn_stage(ksrc, vsrc, kwb[1 - b], vwb[1 - b], (tile + 1) * 64, t);
            CP_WAIT(1);
        } else {
            CP_WAIT(0);
        }
        __syncthreads();

        const uint32_t ksb = kwb[b], vsb = vwb[b];

        // S = Q K^T
        float s_acc[8][4];
#pragma unroll
        for (int nt = 0; nt < 8; nt++)
#pragma unroll
            for (int c = 0; c < 4; c++) s_acc[nt][c] = 0.0f;
#pragma unroll
        for (int ks = 0; ks < 8; ks++) {
#pragma unroll
            for (int j = 0; j < 4; j++) {
                uint32_t b0, b1, b2, b3;
                ldsm4(b0, b1, b2, b3,
                      ksb + (uint32_t)((16 * j + k_row) * ASTR + 16 * ks + k_half) * 2);
                mma16(s_acc[2 * j],     qa[ks], b0, b1);
                mma16(s_acc[2 * j + 1], qa[ks], b2, b3);
            }
        }

        // fixed-shift softmax: p = exp(s*sc - SHIFT); masked cols -> 0
        const int kb = tile * 64;
#pragma unroll
        for (int nt = 0; nt < 8; nt++) {
            const int key0 = kb + nt * 8 + 2 * tg;
            const bool ok0 = key0 < Lw, ok1 = (key0 + 1) < Lw;
            const float p0 = ok0 ? __expf(s_acc[nt][0] * sc - SOFTMAX_SHIFT) : 0.0f;
            const float p1 = ok1 ? __expf(s_acc[nt][1] * sc - SOFTMAX_SHIFT) : 0.0f;
            const float p2 = ok0 ? __expf(s_acc[nt][2] * sc - SOFTMAX_SHIFT) : 0.0f;
            const float p3 = ok1 ? __expf(s_acc[nt][3] * sc - SOFTMAX_SHIFT) : 0.0f;
            s_acc[nt][0] = p0; s_acc[nt][1] = p1;
            s_acc[nt][2] = p2; s_acc[nt][3] = p3;
            lA += p0 + p1;
            lB += p2 + p3;
        }

        // O += P V  (A-fragments from registers)
#pragma unroll
        for (int ks = 0; ks < 4; ks++) {
            uint32_t ap[4];
            ap[0] = pkh(s_acc[2 * ks][0],     s_acc[2 * ks][1]);
            ap[1] = pkh(s_acc[2 * ks][2],     s_acc[2 * ks][3]);
            ap[2] = pkh(s_acc[2 * ks + 1][0], s_acc[2 * ks + 1][1]);
            ap[3] = pkh(s_acc[2 * ks + 1][2], s_acc[2 * ks + 1][3]);
#pragma unroll
            for (int j = 0; j < 8; j++) {
                uint32_t b0, b1, b2, b3;
                ldsm4t(b0, b1, b2, b3,
                       vsb + (uint32_t)((16 * ks + v_row) * ASTR + 16 * j + v_dim) * 2);
                mma16(o_acc[2 * j],     ap, b0, b1);
                mma16(o_acc[2 * j + 1], ap, b2, b3);
            }
        }
        __syncthreads();
    }

    // single row-sum reduction at the end (4 lanes share a row)
    lA += __shfl_xor_sync(0xffffffffu, lA, 1);
    lA += __shfl_xor_sync(0xffffffffu, lA, 2);
    lB += __shfl_xor_sync(0xffffffffu, lB, 1);
    lB += __shfl_xor_sync(0xffffffffu, lB, 2);

    const float iA = 1.0f / lA, iB = 1.0f / lB;
#pragma unroll
    for (int nt = 0; nt < 16; nt++) {
        const int cc = hh * HD + nt * 8 + 2 * tg;
        if (r0ok)
            *(uint32_t*)&o16[(size_t)row0 * DIM + cc] = pkh(o_acc[nt][0] * iA, o_acc[nt][1] * iA);
        if (r1ok)
            *(uint32_t*)&o16[(size_t)(row0 + 8) * DIM + cc] = pkh(o_acc[nt][2] * iB, o_acc[nt][3] * iB);
    }
}

// ---------------------------------------------------------------------------
extern "C" void kernel_launch(void* const* d_in, const int* in_sizes, int n_in,
                              void* d_out, int out_size)
{
    const float* x      = (const float*)d_in[0];
    const float* freqs  = (const float*)d_in[1];
    const float* wq     = (const float*)d_in[2];
    const float* bq     = (const float*)d_in[3];
    const float* wk     = (const float*)d_in[4];
    const float* bk     = (const float*)d_in[5];
    const float* wv     = (const float*)d_in[6];
    const float* bv     = (const float*)d_in[7];
    const float* wo     = (const float*)d_in[8];
    const float* bo     = (const float*)d_in[9];
    const float* gq     = (const float*)d_in[10];
    const float* gk     = (const float*)d_in[11];
    const float* kcache = (const float*)d_in[12];
    const float* vcache = (const float*)d_in[13];
    const int* grid_sizes = (const int*)d_in[14];
    const int* cur_start  = (const int*)d_in[16];

    const int S = in_sizes[0] / DIM;

    float *q, *k, *v;
    __half *x16, *q16, *o16, *wq16, *wk16, *wv16, *wo16, *ku, *vu;
    cudaGetSymbolAddress((void**)&q, g_q);
    cudaGetSymbolAddress((void**)&k, g_k);
    cudaGetSymbolAddress((void**)&v, g_v);
    cudaGetSymbolAddress((void**)&x16, g_x16);
    cudaGetSymbolAddress((void**)&q16, g_q16);
    cudaGetSymbolAddress((void**)&o16, g_o16);
    cudaGetSymbolAddress((void**)&wq16, g_wq16);
    cudaGetSymbolAddress((void**)&wk16, g_wk16);
    cudaGetSymbolAddress((void**)&wv16, g_wv16);
    cudaGetSymbolAddress((void**)&wo16, g_wo16);
    cudaGetSymbolAddress((void**)&ku, g_ku);
    cudaGetSymbolAddress((void**)&vu, g_vu);

    const int wn4 = DIM * DIM / 4;
    const int xn4 = S * DIM / 4;
    const int cvb = ((xn4 > wn4 ? xn4 : wn4) + 255) / 256;
    cvt16_all<<<dim3(cvb, 5), 256>>>(x, x16, xn4, wq, wq16, wk, wk16, wv, wv16, wo, wo16, wn4);

    // fused QKV projections
    gemm_h16<<<dim3((S + 127) / 128, DIM / 128, 3), 256>>>(
        x16, wq16, bq, q, wk16, bk, k, wv16, bv, v, S);

    // fused RMSNorm+RoPE + KV materialization (concurrent in one launch)
    rope_fill<<<2 * S + FILLB, 256>>>(q, k, q16, ku, vu, gq, gk, freqs,
                                      grid_sizes, kcache, vcache, v, cur_start, S);

    const int asmem = 4 * ABUF * 2;   // 69632 B
    cudaFuncSetAttribute(attn_h16, cudaFuncAttributeMaxDynamicSharedMemorySize, asmem);
    attn_h16<<<dim3((S + 63) / 64, NH), 128, asmem>>>(q16, ku, vu, o16, cur_start, S);

    // output projection
    gemm_h16<<<dim3((S + 127) / 128, DIM / 128, 1), 256>>>(
        o16, wo16, bo, (float*)d_out, wo16, bo, (float*)d_out, wo16, bo, (float*)d_out, S);
}